// round 10
// baseline (speedup 1.0000x reference)
#include <cuda_runtime.h>
#include <cuda_fp16.h>
#include <cstdint>

// R10: warp-local MLP; L1 f16 MMA, L2/L3 e4m3 fp8 MMA (m16n8k32, f32 accum,
// bias-initialized). Activation repack f16->e4m3 A-frags via shfl/selp/prmt.

#define SP    262144
#define TB    256
#define GRID  512
#define TILES 8          // 512*8*128 = 524288 voxels

// smem offsets
#define O_W2T8 0         // 1024 entries * 16 B (sx<4, tp<8, lane)
#define O_W3T8 16384     // 512 * 16 (sx<4, tp<4, lane)
#define O_W1T  24576     // 256 * 8 (f16 k8 frags)
#define O_B1H  26624     // 64 * 4 (f16x2)
#define O_B2F  26880     // 64 * 8 (f32 pairs)
#define O_B3F  27392     // 32 * 8
#define O_W4H  27648     // 96 * 4 (f16x2, pre-scaled by 0.1)
#define O_B4   28032     // 3 f32 (pre-scaled by 0.1)
#define SMEM_BYTES 28048

#define MMAH8(c0, c1, a0, a1, b0) asm volatile( \
    "mma.sync.aligned.m16n8k8.row.col.f16.f16.f16.f16 " \
    "{%0,%1}, {%2,%3}, {%4}, {%0,%1};" \
    : "+r"(c0), "+r"(c1) : "r"(a0), "r"(a1), "r"(b0))

#define MMAQ(c, a0, a1, a2, a3, b0, b1) asm volatile( \
    "mma.sync.aligned.m16n8k32.row.col.f32.e4m3.e4m3.f32 " \
    "{%0,%1,%2,%3}, {%4,%5,%6,%7}, {%8,%9}, {%0,%1,%2,%3};" \
    : "+f"((c)[0]), "+f"((c)[1]), "+f"((c)[2]), "+f"((c)[3]) \
    : "r"(a0), "r"(a1), "r"(a2), "r"(a3), "r"(b0), "r"(b1))

__device__ __forceinline__ uint32_t smem_u32(const void* p) {
    uint32_t a;
    asm("{ .reg .u64 t; cvta.to.shared.u64 t, %1; cvt.u32.u64 %0, t; }" : "=r"(a) : "l"(p));
    return a;
}
__device__ __forceinline__ uint32_t lds32(uint32_t a) {
    uint32_t v; asm volatile("ld.shared.b32 %0, [%1];" : "=r"(v) : "r"(a)); return v;
}
__device__ __forceinline__ uint2 lds64(uint32_t a) {
    uint2 v; asm volatile("ld.shared.v2.b32 {%0,%1}, [%2];" : "=r"(v.x), "=r"(v.y) : "r"(a)); return v;
}
__device__ __forceinline__ uint4 lds128(uint32_t a) {
    uint4 v;
    asm volatile("ld.shared.v4.b32 {%0,%1,%2,%3}, [%4];"
                 : "=r"(v.x), "=r"(v.y), "=r"(v.z), "=r"(v.w) : "r"(a));
    return v;
}
__device__ __forceinline__ uint32_t packh(float a, float b) {
    __half2 h = __floats2half2_rn(a, b);
    return *(uint32_t*)&h;
}
__device__ __forceinline__ uint32_t prmt(uint32_t a, uint32_t b, uint32_t s) {
    uint32_t d;
    asm("prmt.b32 %0, %1, %2, %3;" : "=r"(d) : "r"(a), "r"(b), "r"(s));
    return d;
}
// f32 pair -> e4m3x2 (16-bit): low byte = a, high = b
__device__ __forceinline__ uint16_t e4m3x2_f32(float a, float b) {
    uint16_t d;
    asm("cvt.rn.satfinite.e4m3x2.f32 %0, %1, %2;" : "=h"(d) : "f"(b), "f"(a));
    return d;
}
// f16x2 -> e4m3x2
__device__ __forceinline__ uint16_t e4m3x2_h2(uint32_t h2) {
    uint16_t d;
    asm("cvt.rn.satfinite.e4m3x2.f16x2 %0, %1;" : "=h"(d) : "r"(h2));
    return d;
}
// gelu(tanh) on packed f16x2 (no bias)
__device__ __forceinline__ uint32_t gel(uint32_t xu) {
    __half2 x = *(__half2*)&xu;
    const __half2 c0 = __float2half2_rn(0.7978845608f);
    const __half2 c1 = __float2half2_rn(0.03567740814f);
    __half2 u = __hmul2(x, x);
    __half2 z = __hmul2(x, __hfma2(u, c1, c0));
    uint32_t zi = *(uint32_t*)&z, ti;
    asm("tanh.approx.f16x2 %0, %1;" : "=r"(ti) : "r"(zi));
    __half2 t = *(__half2*)&ti;
    __half2 hh = __hmul2(x, __float2half2_rn(0.5f));
    __half2 g = __hfma2(hh, t, hh);
    return *(uint32_t*)&g;
}
__device__ __forceinline__ uint32_t gb(uint32_t cu, uint32_t bu) {
    __half2 x = __hadd2(*(__half2*)&cu, *(__half2*)&bu);
    return gel(*(uint32_t*)&x);
}

// Repack: from v[] (e4m3x4: bytes {f,f+1 row r; f,f+1 row r+8}, f=8t+2q) build
// fp8 A-frags A0..A3 for k-chunk S=32*sx of a 128-feature activation set.
#define CONV_AFRAG(v, sx, A0, A1, A2, A3) do {                                   \
    uint32_t u0A = __shfl_sync(0xffffffffu, (v)[4*(sx)+0], srcA);                \
    uint32_t u1A = __shfl_sync(0xffffffffu, (v)[4*(sx)+1], srcA);                \
    uint32_t u0B = __shfl_sync(0xffffffffu, (v)[4*(sx)+0], srcB);                \
    uint32_t u1B = __shfl_sync(0xffffffffu, (v)[4*(sx)+1], srcB);                \
    uint32_t u2A = __shfl_sync(0xffffffffu, (v)[4*(sx)+2], srcA);                \
    uint32_t u3A = __shfl_sync(0xffffffffu, (v)[4*(sx)+3], srcA);                \
    uint32_t u2B = __shfl_sync(0xffffffffu, (v)[4*(sx)+2], srcB);                \
    uint32_t u3B = __shfl_sync(0xffffffffu, (v)[4*(sx)+3], srcB);                \
    uint32_t x  = jhi ? u1A : u0A;                                               \
    uint32_t y  = jhi ? u1B : u0B;                                               \
    uint32_t x2 = jhi ? u3A : u2A;                                               \
    uint32_t y2 = jhi ? u3B : u2B;                                               \
    A0 = prmt(x,  y,  0x5410u);                                                  \
    A1 = prmt(x,  y,  0x7632u);                                                  \
    A2 = prmt(x2, y2, 0x5410u);                                                  \
    A3 = prmt(x2, y2, 0x7632u);                                                  \
} while (0)

__global__ void __launch_bounds__(TB, 2)
mhd_q8(const float* __restrict__ flow, const float* __restrict__ Bf,
       const float* __restrict__ W1, const float* __restrict__ b1,
       const float* __restrict__ W2, const float* __restrict__ b2,
       const float* __restrict__ W3, const float* __restrict__ b3,
       const float* __restrict__ W4, const float* __restrict__ b4,
       float* __restrict__ out)
{
    extern __shared__ char smc[];
    const int tid  = threadIdx.x;
    const int wid  = tid >> 5;
    const int lane = tid & 31;
    const int q    = lane & 3;
    const int rsub = lane >> 2;
    const uint32_t smb = smem_u32(smc);

    // ---------------- stage weights (once per CTA) ----------------
    // W2 fp8 B-frags: entry e = (sx*8+tp)*32+lane; bytes i of each reg = k 4q+i
    for (int e = tid; e < 1024; e += TB) {
        int l = e & 31, tp = (e >> 5) & 7, sx = e >> 8;
        int n0 = 2 * tp * 8 + (l >> 2), n1 = n0 + 8;
        int kb = sx * 32 + (l & 3) * 4;
        uint4 v;
        v.x = (uint32_t)e4m3x2_f32(W2[kb * 128 + n0], W2[(kb + 1) * 128 + n0])
            | ((uint32_t)e4m3x2_f32(W2[(kb + 2) * 128 + n0], W2[(kb + 3) * 128 + n0]) << 16);
        v.y = (uint32_t)e4m3x2_f32(W2[(kb + 16) * 128 + n0], W2[(kb + 17) * 128 + n0])
            | ((uint32_t)e4m3x2_f32(W2[(kb + 18) * 128 + n0], W2[(kb + 19) * 128 + n0]) << 16);
        v.z = (uint32_t)e4m3x2_f32(W2[kb * 128 + n1], W2[(kb + 1) * 128 + n1])
            | ((uint32_t)e4m3x2_f32(W2[(kb + 2) * 128 + n1], W2[(kb + 3) * 128 + n1]) << 16);
        v.w = (uint32_t)e4m3x2_f32(W2[(kb + 16) * 128 + n1], W2[(kb + 17) * 128 + n1])
            | ((uint32_t)e4m3x2_f32(W2[(kb + 18) * 128 + n1], W2[(kb + 19) * 128 + n1]) << 16);
        *(uint4*)(smc + O_W2T8 + e * 16) = v;
    }
    // W3 fp8 B-frags: e = (sx*4+tp)*32+lane
    for (int e = tid; e < 512; e += TB) {
        int l = e & 31, tp = (e >> 5) & 3, sx = e >> 7;
        int n0 = 2 * tp * 8 + (l >> 2), n1 = n0 + 8;
        int kb = sx * 32 + (l & 3) * 4;
        uint4 v;
        v.x = (uint32_t)e4m3x2_f32(W3[kb * 64 + n0], W3[(kb + 1) * 64 + n0])
            | ((uint32_t)e4m3x2_f32(W3[(kb + 2) * 64 + n0], W3[(kb + 3) * 64 + n0]) << 16);
        v.y = (uint32_t)e4m3x2_f32(W3[(kb + 16) * 64 + n0], W3[(kb + 17) * 64 + n0])
            | ((uint32_t)e4m3x2_f32(W3[(kb + 18) * 64 + n0], W3[(kb + 19) * 64 + n0]) << 16);
        v.z = (uint32_t)e4m3x2_f32(W3[kb * 64 + n1], W3[(kb + 1) * 64 + n1])
            | ((uint32_t)e4m3x2_f32(W3[(kb + 2) * 64 + n1], W3[(kb + 3) * 64 + n1]) << 16);
        v.w = (uint32_t)e4m3x2_f32(W3[(kb + 16) * 64 + n1], W3[(kb + 17) * 64 + n1])
            | ((uint32_t)e4m3x2_f32(W3[(kb + 18) * 64 + n1], W3[(kb + 19) * 64 + n1]) << 16);
        *(uint4*)(smc + O_W3T8 + e * 16) = v;
    }
    // W1 f16 k8 frags (k>=6 zero): e = tp*32+lane
    for (int e = tid; e < 256; e += TB) {
        int l = e & 31, tp = e >> 5;
        int n0 = 2 * tp * 8 + (l >> 2), n1 = n0 + 8;
        int k0 = (l & 3) * 2;
        float a0 = (k0 < 6) ? W1[k0 * 128 + n0] : 0.f;
        float a1 = (k0 + 1 < 6) ? W1[(k0 + 1) * 128 + n0] : 0.f;
        float a2 = (k0 < 6) ? W1[k0 * 128 + n1] : 0.f;
        float a3 = (k0 + 1 < 6) ? W1[(k0 + 1) * 128 + n1] : 0.f;
        uint2 v; v.x = packh(a0, a1); v.y = packh(a2, a3);
        *(uint2*)(smc + O_W1T + e * 8) = v;
    }
    for (int i = tid; i < 64; i += TB)
        *(uint32_t*)(smc + O_B1H + i * 4) = packh(b1[(i >> 2) * 8 + (i & 3) * 2],
                                                  b1[(i >> 2) * 8 + (i & 3) * 2 + 1]);
    for (int i = tid; i < 64; i += TB) {
        int n = (i >> 2) * 8 + (i & 3) * 2;
        *(float2*)(smc + O_B2F + i * 8) = make_float2(b2[n], b2[n + 1]);
    }
    for (int i = tid; i < 32; i += TB) {
        int n = (i >> 2) * 8 + (i & 3) * 2;
        *(float2*)(smc + O_B3F + i * 8) = make_float2(b3[n], b3[n + 1]);
    }
    for (int i = tid; i < 96; i += TB) {   // 0.1*W4, pairs over rows
        int c = i >> 5, p = i & 31;
        *(uint32_t*)(smc + O_W4H + i * 4) = packh(0.1f * W4[2 * p * 3 + c],
                                                  0.1f * W4[(2 * p + 1) * 3 + c]);
    }
    if (tid < 3) ((float*)(smc + O_B4))[tid] = 0.1f * b4[tid];
    __syncthreads();   // only block barrier

    const int srcA = (rsub << 2) + ((q & 1) << 1);
    const int srcB = srcA + 1;
    const bool jhi = (q >> 1) != 0;

    for (int it = 0; it < TILES; it++) {
        const int tile = it * GRID + blockIdx.x;
        const int vbase = tile * 128 + wid * 16;
        const int b  = vbase >> 18;
        const int sb = vbase & (SP - 1);
        const float* Fb = flow + b * 3 * SP;
        const float* Bx = Bf + b * 3 * SP;
        const float* By = Bx + SP;
        const float* Bz = Bx + 2 * SP;

        // ---------------- P0: features + lorentz ----------------
        const int s0 = sb + rsub, s1 = s0 + 8;
        uint32_t fa0, fa1;
        {
            float l0, h0, l1, h1;
            if (q == 0)      { l0 = Fb[s0]; h0 = Fb[SP + s0]; l1 = Fb[s1]; h1 = Fb[SP + s1]; }
            else if (q == 1) { l0 = Fb[2 * SP + s0]; h0 = Bx[s0]; l1 = Fb[2 * SP + s1]; h1 = Bx[s1]; }
            else if (q == 2) { l0 = By[s0]; h0 = Bz[s0]; l1 = By[s1]; h1 = Bz[s1]; }
            else             { l0 = h0 = l1 = h1 = 0.f; }
            fa0 = packh(l0, h0);
            fa1 = packh(l1, h1);
        }
        float lxv = 0.f, lyv = 0.f, lzv = 0.f;
        if (lane < 16) {
            const int sm = sb + lane;
            const int h = sm >> 12, w = (sm >> 6) & 63, d = sm & 63;
            const int H = h << 12, Wo = w << 6;
            const int hp = ((h + 1) & 63) << 12, hm = ((h - 1) & 63) << 12;
            const int wp = ((w + 1) & 63) << 6,  wm2 = ((w - 1) & 63) << 6;
            const int dp = (d + 1) & 63, dm = (d - 1) & 63;
            const float bx = Bx[H + Wo + d], by = By[H + Wo + d], bz = Bz[H + Wo + d];
            const float Jx = 0.5f * ((Bz[H + wp + d] - Bz[H + wm2 + d]) - (By[H + Wo + dp] - By[H + Wo + dm]));
            const float Jy = 0.5f * ((Bx[H + Wo + dp] - Bx[H + Wo + dm]) - (Bz[hp + Wo + d] - Bz[hm + Wo + d]));
            const float Jz = 0.5f * ((By[hp + Wo + d] - By[hm + Wo + d]) - (Bx[H + wp + d] - Bx[H + wm2 + d]));
            lxv = (Jy * bz - Jz * by) * 2500.0f;
            lyv = (Jz * bx - Jx * bz) * 2500.0f;
            lzv = (Jx * by - Jy * bx) * 2500.0f;
        }

        // ---------------- L1 (f16 k8): 6 -> 128 ----------------
        uint32_t v1[16];
        {
            uint32_t c1[16][2];
            #pragma unroll
            for (int t = 0; t < 16; t++) { c1[t][0] = 0u; c1[t][1] = 0u; }
            #pragma unroll
            for (int tp = 0; tp < 8; tp++) {
                uint2 B1f = lds64(smb + O_W1T + (uint32_t)(tp * 32 + lane) * 8);
                MMAH8(c1[2 * tp][0], c1[2 * tp][1], fa0, fa1, B1f.x);
                MMAH8(c1[2 * tp + 1][0], c1[2 * tp + 1][1], fa0, fa1, B1f.y);
            }
            #pragma unroll
            for (int t = 0; t < 16; t++) {
                uint32_t bb = lds32(smb + O_B1H + (uint32_t)(t * 4 + q) * 4);
                uint32_t g0 = gb(c1[t][0], bb);
                uint32_t g1 = gb(c1[t][1], bb);
                v1[t] = (uint32_t)e4m3x2_h2(g0) | ((uint32_t)e4m3x2_h2(g1) << 16);
            }
        }

        // ---------------- L2 (fp8): 128 -> 128, bias-initialized f32 accum ----
        uint32_t v2[16];
        {
            float c2[16][4];
            #pragma unroll
            for (int t = 0; t < 16; t++) {
                uint2 bf = lds64(smb + O_B2F + (uint32_t)(t * 4 + q) * 8);
                c2[t][0] = __uint_as_float(bf.x);
                c2[t][1] = __uint_as_float(bf.y);
                c2[t][2] = __uint_as_float(bf.x);
                c2[t][3] = __uint_as_float(bf.y);
            }
            #pragma unroll
            for (int sx = 0; sx < 4; sx++) {
                uint32_t A0, A1, A2, A3;
                CONV_AFRAG(v1, sx, A0, A1, A2, A3);
                #pragma unroll
                for (int tp = 0; tp < 8; tp++) {
                    uint4 Bq = lds128(smb + O_W2T8 + (uint32_t)((sx * 8 + tp) * 32 + lane) * 16);
                    MMAQ(c2[2 * tp], A0, A1, A2, A3, Bq.x, Bq.y);
                    MMAQ(c2[2 * tp + 1], A0, A1, A2, A3, Bq.z, Bq.w);
                }
            }
            #pragma unroll
            for (int t = 0; t < 16; t++) {
                uint32_t g0 = gel(packh(c2[t][0], c2[t][1]));
                uint32_t g1 = gel(packh(c2[t][2], c2[t][3]));
                v2[t] = (uint32_t)e4m3x2_h2(g0) | ((uint32_t)e4m3x2_h2(g1) << 16);
            }
        }

        // ---------------- L3 (fp8): 128 -> 64 ----------------
        uint32_t x3[8][2];
        {
            float c3[8][4];
            #pragma unroll
            for (int t = 0; t < 8; t++) {
                uint2 bf = lds64(smb + O_B3F + (uint32_t)(t * 4 + q) * 8);
                c3[t][0] = __uint_as_float(bf.x);
                c3[t][1] = __uint_as_float(bf.y);
                c3[t][2] = __uint_as_float(bf.x);
                c3[t][3] = __uint_as_float(bf.y);
            }
            #pragma unroll
            for (int sx = 0; sx < 4; sx++) {
                uint32_t A0, A1, A2, A3;
                CONV_AFRAG(v2, sx, A0, A1, A2, A3);
                #pragma unroll
                for (int tp = 0; tp < 4; tp++) {
                    uint4 Bq = lds128(smb + O_W3T8 + (uint32_t)((sx * 4 + tp) * 32 + lane) * 16);
                    MMAQ(c3[2 * tp], A0, A1, A2, A3, Bq.x, Bq.y);
                    MMAQ(c3[2 * tp + 1], A0, A1, A2, A3, Bq.z, Bq.w);
                }
            }
            #pragma unroll
            for (int t = 0; t < 8; t++) {
                x3[t][0] = gel(packh(c3[t][0], c3[t][1]));
                x3[t][1] = gel(packh(c3[t][2], c3[t][3]));
            }
        }

        // ---------------- L4: 64 -> 3 (pre-scaled by 0.1) + lorentz + store ----
        __half2 acc[2][3];
        #pragma unroll
        for (int r = 0; r < 2; r++)
            #pragma unroll
            for (int cc = 0; cc < 3; cc++) acc[r][cc] = __float2half2_rn(0.f);
        #pragma unroll
        for (int t = 0; t < 8; t++) {
            #pragma unroll
            for (int cc = 0; cc < 3; cc++) {
                uint32_t wu = lds32(smb + O_W4H + (uint32_t)(cc * 32 + t * 4 + q) * 4);
                __half2 wh = *(__half2*)&wu;
                acc[0][cc] = __hfma2(*(__half2*)&x3[t][0], wh, acc[0][cc]);
                acc[1][cc] = __hfma2(*(__half2*)&x3[t][1], wh, acc[1][cc]);
            }
        }
        float pe[2][3];
        #pragma unroll
        for (int r = 0; r < 2; r++)
            #pragma unroll
            for (int cc = 0; cc < 3; cc++) {
                float2 f = __half22float2(acc[r][cc]);
                float vv = f.x + f.y;
                vv += __shfl_xor_sync(0xffffffffu, vv, 1);
                vv += __shfl_xor_sync(0xffffffffu, vv, 2);
                pe[r][cc] = vv + ((const float*)(smc + O_B4))[cc];
            }
        const float Lx0 = __shfl_sync(0xffffffffu, lxv, rsub);
        const float Ly0 = __shfl_sync(0xffffffffu, lyv, rsub);
        const float Lz0 = __shfl_sync(0xffffffffu, lzv, rsub);
        const float Lx1 = __shfl_sync(0xffffffffu, lxv, rsub + 8);
        const float Ly1 = __shfl_sync(0xffffffffu, lyv, rsub + 8);
        const float Lz1 = __shfl_sync(0xffffffffu, lzv, rsub + 8);
        if (q < 3) {
            const float L0 = (q == 0) ? Lx0 : (q == 1) ? Ly0 : Lz0;
            const float L1 = (q == 0) ? Lx1 : (q == 1) ? Ly1 : Lz1;
            float* ob = out + b * 3 * SP + q * SP;
            ob[s0] = L0 + pe[0][q];
            ob[s1] = L1 + pe[1][q];
        }
    }
}

extern "C" void kernel_launch(void* const* d_in, const int* in_sizes, int n_in,
                              void* d_out, int out_size)
{
    (void)in_sizes; (void)n_in; (void)out_size;
    cudaFuncSetAttribute(mhd_q8, cudaFuncAttributeMaxDynamicSharedMemorySize, SMEM_BYTES);
    mhd_q8<<<GRID, TB, SMEM_BYTES>>>(
        (const float*)d_in[0], (const float*)d_in[1], (const float*)d_in[2],
        (const float*)d_in[3], (const float*)d_in[4], (const float*)d_in[5],
        (const float*)d_in[6], (const float*)d_in[7], (const float*)d_in[8],
        (const float*)d_in[9], (float*)d_out);
}

// round 11
// speedup vs baseline: 1.3491x; 1.3491x over previous
#include <cuda_runtime.h>
#include <cuda_fp16.h>
#include <cstdint>

// R11 = R9 (warp-local f16 MLP dataflow) + 3 CTAs/SM (__launch_bounds__(256,3),
// ~85 regs) + lorentz stashed in warp-private smem to shrink the live set.

#define SP    262144
#define TB    256
#define GRID  512
#define TILES 8          // 512*8*128 = 524288 voxels

// smem byte offsets
#define O_W2T  0         // 2048 entries * 16 B (sx<8, tp<8, lane)
#define O_W3T  32768     // 1024 * 16 (sx<8, tp<4, lane)
#define O_W1T  49152     // 256 * 8 (f16 k8 frags)
#define O_B1H  51200     // 64 * 4
#define O_B2H  51456     // 64 * 4
#define O_B3H  51712     // 32 * 4
#define O_W4H  51840     // 96 * 4  (c*32 + p)
#define O_B4   52224     // 3 f32 (+pad)
#define O_LZ   52240     // 128 rows * 3 f32 = 1536 (warp-private lorentz stash)
#define SMEM_BYTES 53776

#define MMAH16(c0, c1, a0, a1, a2, a3, b0, b1) asm volatile( \
    "mma.sync.aligned.m16n8k16.row.col.f16.f16.f16.f16 " \
    "{%0,%1}, {%2,%3,%4,%5}, {%6,%7}, {%0,%1};" \
    : "+r"(c0), "+r"(c1) \
    : "r"(a0), "r"(a1), "r"(a2), "r"(a3), "r"(b0), "r"(b1))

#define MMAH8(c0, c1, a0, a1, b0) asm volatile( \
    "mma.sync.aligned.m16n8k8.row.col.f16.f16.f16.f16 " \
    "{%0,%1}, {%2,%3}, {%4}, {%0,%1};" \
    : "+r"(c0), "+r"(c1) : "r"(a0), "r"(a1), "r"(b0))

__device__ __forceinline__ uint32_t smem_u32(const void* p) {
    uint32_t a;
    asm("{ .reg .u64 t; cvta.to.shared.u64 t, %1; cvt.u32.u64 %0, t; }" : "=r"(a) : "l"(p));
    return a;
}
__device__ __forceinline__ uint32_t lds32(uint32_t a) {
    uint32_t v; asm volatile("ld.shared.b32 %0, [%1];" : "=r"(v) : "r"(a)); return v;
}
__device__ __forceinline__ uint2 lds64(uint32_t a) {
    uint2 v; asm volatile("ld.shared.v2.b32 {%0,%1}, [%2];" : "=r"(v.x), "=r"(v.y) : "r"(a)); return v;
}
__device__ __forceinline__ uint4 lds128(uint32_t a) {
    uint4 v;
    asm volatile("ld.shared.v4.b32 {%0,%1,%2,%3}, [%4];"
                 : "=r"(v.x), "=r"(v.y), "=r"(v.z), "=r"(v.w) : "r"(a));
    return v;
}
__device__ __forceinline__ uint32_t packh(float a, float b) {
    __half2 h = __floats2half2_rn(a, b);
    return *(uint32_t*)&h;
}
// bias-add + gelu(tanh) on packed f16x2
__device__ __forceinline__ uint32_t gb(uint32_t cu, uint32_t bu) {
    __half2 x = __hadd2(*(__half2*)&cu, *(__half2*)&bu);
    const __half2 c0 = __float2half2_rn(0.7978845608f);
    const __half2 c1 = __float2half2_rn(0.03567740814f);
    __half2 u = __hmul2(x, x);
    __half2 z = __hmul2(x, __hfma2(u, c1, c0));
    uint32_t zi = *(uint32_t*)&z, ti;
    asm("tanh.approx.f16x2 %0, %1;" : "=r"(ti) : "r"(zi));
    __half2 t = *(__half2*)&ti;
    __half2 hh = __hmul2(x, __float2half2_rn(0.5f));
    __half2 g = __hfma2(hh, t, hh);
    return *(uint32_t*)&g;
}

__global__ void __launch_bounds__(TB, 3)
mhd_wl3(const float* __restrict__ flow, const float* __restrict__ Bf,
        const float* __restrict__ W1, const float* __restrict__ b1,
        const float* __restrict__ W2, const float* __restrict__ b2,
        const float* __restrict__ W3, const float* __restrict__ b3,
        const float* __restrict__ W4, const float* __restrict__ b4,
        float* __restrict__ out)
{
    extern __shared__ char smc[];
    const int tid  = threadIdx.x;
    const int wid  = tid >> 5;
    const int lane = tid & 31;
    const int q    = lane & 3;
    const int rsub = lane >> 2;
    const uint32_t smb = smem_u32(smc);

    // ---------------- stage weight B-fragment tables (once per CTA) ----------------
    for (int e = tid; e < 2048; e += TB) {      // W2T
        int l = e & 31, tp = (e >> 5) & 7, sx = e >> 8;
        int n0 = (2 * tp) * 8 + (l >> 2), n1 = n0 + 8;
        int k0 = sx * 16 + (l & 3) * 2;
        uint4 v;
        v.x = packh(W2[k0 * 128 + n0],       W2[(k0 + 1) * 128 + n0]);
        v.y = packh(W2[(k0 + 8) * 128 + n0], W2[(k0 + 9) * 128 + n0]);
        v.z = packh(W2[k0 * 128 + n1],       W2[(k0 + 1) * 128 + n1]);
        v.w = packh(W2[(k0 + 8) * 128 + n1], W2[(k0 + 9) * 128 + n1]);
        *(uint4*)(smc + O_W2T + e * 16) = v;
    }
    for (int e = tid; e < 1024; e += TB) {      // W3T
        int l = e & 31, tp = (e >> 5) & 3, sx = e >> 7;
        int n0 = (2 * tp) * 8 + (l >> 2), n1 = n0 + 8;
        int k0 = sx * 16 + (l & 3) * 2;
        uint4 v;
        v.x = packh(W3[k0 * 64 + n0],       W3[(k0 + 1) * 64 + n0]);
        v.y = packh(W3[(k0 + 8) * 64 + n0], W3[(k0 + 9) * 64 + n0]);
        v.z = packh(W3[k0 * 64 + n1],       W3[(k0 + 1) * 64 + n1]);
        v.w = packh(W3[(k0 + 8) * 64 + n1], W3[(k0 + 9) * 64 + n1]);
        *(uint4*)(smc + O_W3T + e * 16) = v;
    }
    for (int e = tid; e < 256; e += TB) {       // W1T (k>=6 zero)
        int l = e & 31, tp = e >> 5;
        int n0 = (2 * tp) * 8 + (l >> 2), n1 = n0 + 8;
        int k0 = (l & 3) * 2;
        float a0 = (k0 < 6) ? W1[k0 * 128 + n0] : 0.f;
        float a1 = (k0 + 1 < 6) ? W1[(k0 + 1) * 128 + n0] : 0.f;
        float a2 = (k0 < 6) ? W1[k0 * 128 + n1] : 0.f;
        float a3 = (k0 + 1 < 6) ? W1[(k0 + 1) * 128 + n1] : 0.f;
        uint2 v; v.x = packh(a0, a1); v.y = packh(a2, a3);
        *(uint2*)(smc + O_W1T + e * 8) = v;
    }
    for (int i = tid; i < 64; i += TB)
        *(uint32_t*)(smc + O_B1H + i * 4) = packh(b1[(i >> 2) * 8 + (i & 3) * 2],
                                                  b1[(i >> 2) * 8 + (i & 3) * 2 + 1]);
    for (int i = tid; i < 64; i += TB)
        *(uint32_t*)(smc + O_B2H + i * 4) = packh(b2[(i >> 2) * 8 + (i & 3) * 2],
                                                  b2[(i >> 2) * 8 + (i & 3) * 2 + 1]);
    for (int i = tid; i < 32; i += TB)
        *(uint32_t*)(smc + O_B3H + i * 4) = packh(b3[(i >> 2) * 8 + (i & 3) * 2],
                                                  b3[(i >> 2) * 8 + (i & 3) * 2 + 1]);
    for (int i = tid; i < 96; i += TB) {        // W4H[c*32+p] = {W4[2p][c], W4[2p+1][c]}
        int c = i >> 5, p = i & 31;
        *(uint32_t*)(smc + O_W4H + i * 4) = packh(W4[2 * p * 3 + c], W4[(2 * p + 1) * 3 + c]);
    }
    if (tid < 3) ((float*)(smc + O_B4))[tid] = b4[tid];
    __syncthreads();   // only block barrier in the kernel

    for (int it = 0; it < TILES; it++) {
        const int tile = it * GRID + blockIdx.x;
        const int vbase = tile * 128 + wid * 16;   // warp's 16-voxel strip
        const int b  = vbase >> 18;
        const int sb = vbase & (SP - 1);
        const float* Fb = flow + b * 3 * SP;
        const float* Bx = Bf + b * 3 * SP;
        const float* By = Bx + SP;
        const float* Bz = Bx + 2 * SP;

        // ---------------- P0: features into A-frags; lorentz -> smem stash ----
        const int s0 = sb + rsub, s1 = s0 + 8;
        uint32_t fa0, fa1;
        {
            float l0, h0, l1, h1;
            if (q == 0)      { l0 = Fb[s0]; h0 = Fb[SP + s0]; l1 = Fb[s1]; h1 = Fb[SP + s1]; }
            else if (q == 1) { l0 = Fb[2 * SP + s0]; h0 = Bx[s0]; l1 = Fb[2 * SP + s1]; h1 = Bx[s1]; }
            else if (q == 2) { l0 = By[s0]; h0 = Bz[s0]; l1 = By[s1]; h1 = Bz[s1]; }
            else             { l0 = h0 = l1 = h1 = 0.f; }
            fa0 = packh(l0, h0);
            fa1 = packh(l1, h1);
        }
        __syncwarp();          // prev tile's L4 reads of LZ rows complete
        if (lane < 16) {
            const int sm = sb + lane;
            const int h = sm >> 12, w = (sm >> 6) & 63, d = sm & 63;
            const int H = h << 12, Wo = w << 6;
            const int hp = ((h + 1) & 63) << 12, hm = ((h - 1) & 63) << 12;
            const int wp = ((w + 1) & 63) << 6,  wm2 = ((w - 1) & 63) << 6;
            const int dp = (d + 1) & 63, dm = (d - 1) & 63;
            const float bx = Bx[H + Wo + d], by = By[H + Wo + d], bz = Bz[H + Wo + d];
            const float Jx = 0.5f * ((Bz[H + wp + d] - Bz[H + wm2 + d]) - (By[H + Wo + dp] - By[H + Wo + dm]));
            const float Jy = 0.5f * ((Bx[H + Wo + dp] - Bx[H + Wo + dm]) - (Bz[hp + Wo + d] - Bz[hm + Wo + d]));
            const float Jz = 0.5f * ((By[hp + Wo + d] - By[hm + Wo + d]) - (Bx[H + wp + d] - Bx[H + wm2 + d]));
            float* lz = (float*)(smc + O_LZ) + (wid * 16 + lane) * 3;
            lz[0] = (Jy * bz - Jz * by) * 2500.0f;
            lz[1] = (Jz * bx - Jx * bz) * 2500.0f;
            lz[2] = (Jx * by - Jy * bx) * 2500.0f;
        }

        uint32_t a[16][2];    // activations (A-frags / gelu'd C-frags)
        uint32_t c[16][2];    // accumulators

        // ---------------- L1: 6(->8) -> 128, k8 MMA ----------------
        #pragma unroll
        for (int t = 0; t < 16; t++) { c[t][0] = 0u; c[t][1] = 0u; }
        #pragma unroll
        for (int tp = 0; tp < 8; tp++) {
            uint2 B1f = lds64(smb + O_W1T + (uint32_t)(tp * 32 + lane) * 8);
            MMAH8(c[2 * tp][0], c[2 * tp][1], fa0, fa1, B1f.x);
            MMAH8(c[2 * tp + 1][0], c[2 * tp + 1][1], fa0, fa1, B1f.y);
        }
        #pragma unroll
        for (int t = 0; t < 16; t++) {
            uint32_t bb = lds32(smb + O_B1H + (uint32_t)(t * 4 + q) * 4);
            a[t][0] = gb(c[t][0], bb);
            a[t][1] = gb(c[t][1], bb);
        }

        // ---------------- L2: 128 -> 128 ----------------
        #pragma unroll
        for (int t = 0; t < 16; t++) { c[t][0] = 0u; c[t][1] = 0u; }
        #pragma unroll
        for (int sx = 0; sx < 8; sx++) {
            const uint32_t a0 = a[2 * sx][0], a1 = a[2 * sx][1];
            const uint32_t a2 = a[2 * sx + 1][0], a3 = a[2 * sx + 1][1];
            #pragma unroll
            for (int tp = 0; tp < 8; tp++) {
                uint4 Bf2 = lds128(smb + O_W2T + (uint32_t)((sx * 8 + tp) * 32 + lane) * 16);
                MMAH16(c[2 * tp][0], c[2 * tp][1], a0, a1, a2, a3, Bf2.x, Bf2.y);
                MMAH16(c[2 * tp + 1][0], c[2 * tp + 1][1], a0, a1, a2, a3, Bf2.z, Bf2.w);
            }
        }
        #pragma unroll
        for (int t = 0; t < 16; t++) {
            uint32_t bb = lds32(smb + O_B2H + (uint32_t)(t * 4 + q) * 4);
            a[t][0] = gb(c[t][0], bb);
            a[t][1] = gb(c[t][1], bb);
        }

        // ---------------- L3: 128 -> 64 ----------------
        uint32_t c3[8][2];
        #pragma unroll
        for (int t = 0; t < 8; t++) { c3[t][0] = 0u; c3[t][1] = 0u; }
        #pragma unroll
        for (int sx = 0; sx < 8; sx++) {
            const uint32_t a0 = a[2 * sx][0], a1 = a[2 * sx][1];
            const uint32_t a2 = a[2 * sx + 1][0], a3 = a[2 * sx + 1][1];
            #pragma unroll
            for (int tp = 0; tp < 4; tp++) {
                uint4 Bf3 = lds128(smb + O_W3T + (uint32_t)((sx * 4 + tp) * 32 + lane) * 16);
                MMAH16(c3[2 * tp][0], c3[2 * tp][1], a0, a1, a2, a3, Bf3.x, Bf3.y);
                MMAH16(c3[2 * tp + 1][0], c3[2 * tp + 1][1], a0, a1, a2, a3, Bf3.z, Bf3.w);
            }
        }
        #pragma unroll
        for (int t = 0; t < 8; t++) {
            uint32_t bb = lds32(smb + O_B3H + (uint32_t)(t * 4 + q) * 4);
            c3[t][0] = gb(c3[t][0], bb);    // x3 in place
            c3[t][1] = gb(c3[t][1], bb);
        }

        // ---------------- L4: 64 -> 3 (hfma2 dot + quad butterfly) ----------------
        __half2 acc[2][3];
        #pragma unroll
        for (int r = 0; r < 2; r++)
            #pragma unroll
            for (int cc = 0; cc < 3; cc++) acc[r][cc] = __float2half2_rn(0.f);
        #pragma unroll
        for (int t = 0; t < 8; t++) {
            #pragma unroll
            for (int cc = 0; cc < 3; cc++) {
                uint32_t wu = lds32(smb + O_W4H + (uint32_t)(cc * 32 + t * 4 + q) * 4);
                __half2 wh = *(__half2*)&wu;
                acc[0][cc] = __hfma2(*(__half2*)&c3[t][0], wh, acc[0][cc]);
                acc[1][cc] = __hfma2(*(__half2*)&c3[t][1], wh, acc[1][cc]);
            }
        }
        float pe[2][3];
        #pragma unroll
        for (int r = 0; r < 2; r++)
            #pragma unroll
            for (int cc = 0; cc < 3; cc++) {
                float2 f = __half22float2(acc[r][cc]);
                float vv = f.x + f.y;
                vv += __shfl_xor_sync(0xffffffffu, vv, 1);
                vv += __shfl_xor_sync(0xffffffffu, vv, 2);
                pe[r][cc] = vv + ((const float*)(smc + O_B4))[cc];
            }
        __syncwarp();          // LZ stores (lanes 0-15) visible to all lanes
        if (q < 3) {
            const float L0 = ((const float*)(smc + O_LZ))[(wid * 16 + rsub) * 3 + q];
            const float L1 = ((const float*)(smc + O_LZ))[(wid * 16 + rsub + 8) * 3 + q];
            float* ob = out + b * 3 * SP + q * SP;
            ob[s0] = L0 + 0.1f * pe[0][q];
            ob[s1] = L1 + 0.1f * pe[1][q];
        }
    }
}

extern "C" void kernel_launch(void* const* d_in, const int* in_sizes, int n_in,
                              void* d_out, int out_size)
{
    (void)in_sizes; (void)n_in; (void)out_size;
    cudaFuncSetAttribute(mhd_wl3, cudaFuncAttributeMaxDynamicSharedMemorySize, SMEM_BYTES);
    mhd_wl3<<<GRID, TB, SMEM_BYTES>>>(
        (const float*)d_in[0], (const float*)d_in[1], (const float*)d_in[2],
        (const float*)d_in[3], (const float*)d_in[4], (const float*)d_in[5],
        (const float*)d_in[6], (const float*)d_in[7], (const float*)d_in[8],
        (const float*)d_in[9], (float*)d_out);
}